// round 13
// baseline (speedup 1.0000x reference)
#include <cuda_runtime.h>
#include <cuda_fp16.h>
#include <cstdint>

// ---------------- problem dims ----------------
#define M_DIM 4096
#define K_DIM 4096
#define N_DIM 11008

// GEMM tiling: CTA 128x128x64, 4 warps (2M x 2N), warp tile 64x64, 3 CTAs/SM
#define BM 128
#define BN 128
#define BK 64
#define STAGES 2
#define THREADS 128
#define KT (K_DIM / BK)          // 64
#define NT_TILES (N_DIM / BN)    // 86
#define MT_TILES (M_DIM / BM)    // 32
#define GROUP_M 4                // M-tiles grouped per bx for L2 B-reuse

// padded smem rows: 64 halves (128B) + 16B pad = 144B stride
#define ROW_BYTES 144
#define A_STAGE_BYTES (BM * ROW_BYTES)                 // 18432
#define B_STAGE_BYTES (BN * ROW_BYTES)                 // 18432
#define STAGE_BYTES   (A_STAGE_BYTES + B_STAGE_BYTES)  // 36864
#define SMEM_BYTES    (STAGES * STAGE_BYTES)           // 73728 -> 3 CTAs/SM

// dequantized weights fp16 [N_DIM, K_DIM] K-major; x converted to fp16
__device__ __half g_w[(size_t)N_DIM * K_DIM];
__device__ __half g_x[(size_t)M_DIM * K_DIM];

// ---------------- helpers ----------------
__device__ __forceinline__ uint32_t smem_u32(const void* p) {
    return (uint32_t)__cvta_generic_to_shared(p);
}

__device__ __forceinline__ void cp_async16(uint32_t dst, const void* src) {
    asm volatile("cp.async.cg.shared.global [%0], [%1], 16;" :: "r"(dst), "l"(src));
}

__device__ __forceinline__ void ldsm4(uint32_t* r, uint32_t addr) {
    asm volatile("ldmatrix.sync.aligned.m8n8.x4.shared.b16 {%0,%1,%2,%3}, [%4];"
                 : "=r"(r[0]), "=r"(r[1]), "=r"(r[2]), "=r"(r[3]) : "r"(addr));
}

__device__ __forceinline__ void mma16816(float* d, const uint32_t* a, uint32_t b0, uint32_t b1) {
    asm volatile(
        "mma.sync.aligned.m16n8k16.row.col.f32.f16.f16.f32 "
        "{%0,%1,%2,%3}, {%4,%5,%6,%7}, {%8,%9}, {%0,%1,%2,%3};"
        : "+f"(d[0]), "+f"(d[1]), "+f"(d[2]), "+f"(d[3])
        : "r"(a[0]), "r"(a[1]), "r"(a[2]), "r"(a[3]), "r"(b0), "r"(b1));
}

__device__ __forceinline__ unsigned pack_h2(float lo, float hi) {
    __half2 h = __floats2half2_rn(lo, hi);
    return *reinterpret_cast<unsigned*>(&h);
}

// ---------------- kernel 1: fused prep (dequant W + convert x) ----------------
#define DEQ_BLOCKS ((N_DIM * 512) / 256)            // 22016
#define CVT_BLOCKS ((M_DIM * (K_DIM / 8)) / 256)    // 8192

__global__ void __launch_bounds__(256) prep_kernel(const int* __restrict__ qw,
                                                   const float* __restrict__ sc,
                                                   const int* __restrict__ zp,
                                                   const float* __restrict__ xf) {
    if (blockIdx.x < DEQ_BLOCKS) {
        int t = blockIdx.x * 256 + threadIdx.x;
        int o  = t >> 9;
        int p0 = (t & 511) << 2;
        const int4 q4 = *reinterpret_cast<const int4*>(qw + (size_t)o * 2048 + p0);
        int g = p0 >> 6;
        float scale = sc[o * 32 + g];
        float zero  = (float)zp[o * 32 + g];
        int qs[4] = {q4.x, q4.y, q4.z, q4.w};
        uint4 st;
        st.x = pack_h2(((float)(qs[0] & 0xF) - zero) * scale, ((float)((qs[0] >> 4) & 0xF) - zero) * scale);
        st.y = pack_h2(((float)(qs[1] & 0xF) - zero) * scale, ((float)((qs[1] >> 4) & 0xF) - zero) * scale);
        st.z = pack_h2(((float)(qs[2] & 0xF) - zero) * scale, ((float)((qs[2] >> 4) & 0xF) - zero) * scale);
        st.w = pack_h2(((float)(qs[3] & 0xF) - zero) * scale, ((float)((qs[3] >> 4) & 0xF) - zero) * scale);
        *reinterpret_cast<uint4*>(g_w + (size_t)o * K_DIM + 2 * p0) = st;
    } else {
        const size_t i = ((size_t)(blockIdx.x - DEQ_BLOCKS) * 256 + threadIdx.x) * 8;
        const float4 a = *reinterpret_cast<const float4*>(xf + i);
        const float4 b = *reinterpret_cast<const float4*>(xf + i + 4);
        uint4 st;
        st.x = pack_h2(a.x, a.y);
        st.y = pack_h2(a.z, a.w);
        st.z = pack_h2(b.x, b.y);
        st.w = pack_h2(b.z, b.w);
        *reinterpret_cast<uint4*>(g_x + i) = st;
    }
}

// ---------------- kernel 2: pipelined mma.sync GEMM ----------------
// out = f16(f16(x @ w^T) + bias) upcast to fp32. CTA 128x128x64,
// 4 warps (2M x 2N), warp tile 64x64, 2-stage smem pipeline, 3 CTAs/SM.
// kt body: j=0 ldsm first (tensor starts early), then next-stage cp.async.
// 1D grid with GROUP_M swizzle: 4 consecutive CTAs share one B tile (L2 reuse).

__device__ __forceinline__ uint32_t row_addr(uint32_t base, int row, int kc) {
    return base + row * ROW_BYTES + kc * 16;
}

__global__ void __launch_bounds__(THREADS, 3) gemm_kernel(
    const float* __restrict__ bias,
    float* __restrict__ out)
{
    extern __shared__ char smem[];
    const uint32_t sb = smem_u32(smem);

    const int tid  = threadIdx.x;
    const int wid  = tid >> 5;
    const int lane = tid & 31;
    const int wm = wid >> 1;        // 0..1  (M)
    const int wn = wid & 1;         // 0..1  (N)

    // swizzled tile mapping: groups of GROUP_M M-tiles per bx stripe
    const int id    = blockIdx.x;
    const int group = id / (GROUP_M * NT_TILES);
    const int rem   = id % (GROUP_M * NT_TILES);
    const int by    = group * GROUP_M + (rem % GROUP_M);   // 0..31
    const int bx    = rem / GROUP_M;                       // 0..85

    const __half* Ag = g_x + (size_t)(by * BM) * K_DIM;
    const __half* Bg = g_w + (size_t)(bx * BN) * K_DIM;

    const int ld_row = tid >> 3;        // 0..15 (+16 per i)
    const int ld_kc  = tid & 7;         // 16B chunk 0..7

    // prologue: fill stage 0
    {
        const uint32_t ab = sb;
        const uint32_t bb = ab + A_STAGE_BYTES;
        #pragma unroll
        for (int i = 0; i < 8; i++) {
            int row = ld_row + i * 16;
            cp_async16(row_addr(ab, row, ld_kc), Ag + (size_t)row * K_DIM + ld_kc * 8);
            cp_async16(row_addr(bb, row, ld_kc), Bg + (size_t)row * K_DIM + ld_kc * 8);
        }
        asm volatile("cp.async.commit_group;");
    }

    float acc[4][8][4];
    #pragma unroll
    for (int i = 0; i < 4; i++)
        #pragma unroll
        for (int j = 0; j < 8; j++)
            #pragma unroll
            for (int k = 0; k < 4; k++) acc[i][j][k] = 0.f;

    const int g  = lane >> 3;       // ldmatrix matrix-group 0..3
    const int r8 = lane & 7;

    const int a_row_off = wm * 64 + ((g & 1) << 3) + r8;   // + mt*16
    const int b_row_off = wn * 64 + ((g & 2) << 2) + r8;   // + bt*16
    const int a_kc_sel  = (g >> 1);                        // + 2j
    const int b_kc_sel  = (g & 1);                         // + 2j

    for (int kt = 0; kt < KT; kt++) {
        asm volatile("cp.async.wait_group 0;");
        __syncthreads();

        const int s = kt & 1;
        const uint32_t abase = sb + s * STAGE_BYTES;
        const uint32_t bbase = abase + A_STAGE_BYTES;

        // j = 0 fragments FIRST so HMMAs start before the prefetch burst
        uint32_t a_frag[4][4];
        #pragma unroll
        for (int mt = 0; mt < 4; mt++)
            ldsm4(a_frag[mt], row_addr(abase, a_row_off + mt * 16, a_kc_sel));
        uint32_t b0_frag[4][4];
        #pragma unroll
        for (int bt = 0; bt < 4; bt++)
            ldsm4(b0_frag[bt], row_addr(bbase, b_row_off + bt * 16, b_kc_sel));

        // prefetch stage kt+1 into the other buffer (readers done, per barrier above)
        if (kt + 1 < KT) {
            const uint32_t ab = sb + (s ^ 1) * STAGE_BYTES;
            const uint32_t bb = ab + A_STAGE_BYTES;
            const int kofs = (kt + 1) * BK;
            #pragma unroll
            for (int i = 0; i < 8; i++) {
                int row = ld_row + i * 16;
                cp_async16(row_addr(ab, row, ld_kc), Ag + (size_t)row * K_DIM + kofs + ld_kc * 8);
                cp_async16(row_addr(bb, row, ld_kc), Bg + (size_t)row * K_DIM + kofs + ld_kc * 8);
            }
        }
        asm volatile("cp.async.commit_group;");

        // j = 0 MMAs (fragments already in flight)
        #pragma unroll
        for (int bt = 0; bt < 4; bt++) {
            #pragma unroll
            for (int mt = 0; mt < 4; mt++) {
                mma16816(acc[mt][bt * 2 + 0], a_frag[mt], b0_frag[bt][0], b0_frag[bt][1]);
                mma16816(acc[mt][bt * 2 + 1], a_frag[mt], b0_frag[bt][2], b0_frag[bt][3]);
            }
        }

        // j = 1..3 (R11 structure: per-bt B loads, ptxas schedules the overlap)
        #pragma unroll
        for (int j = 1; j < 4; j++) {
            const int akc = 2 * j + a_kc_sel;
            const int bkc = 2 * j + b_kc_sel;
            #pragma unroll
            for (int mt = 0; mt < 4; mt++)
                ldsm4(a_frag[mt], row_addr(abase, a_row_off + mt * 16, akc));
            #pragma unroll
            for (int bt = 0; bt < 4; bt++) {
                uint32_t b_frag[4];
                ldsm4(b_frag, row_addr(bbase, b_row_off + bt * 16, bkc));
                #pragma unroll
                for (int mt = 0; mt < 4; mt++) {
                    mma16816(acc[mt][bt * 2 + 0], a_frag[mt], b_frag[0], b_frag[1]);
                    mma16816(acc[mt][bt * 2 + 1], a_frag[mt], b_frag[2], b_frag[3]);
                }
            }
        }
    }

    // ---- epilogue: round like the reference (f16 matmul result, then f16 +bias) ----
    const int mbase = by * BM + wm * 64;
    const int nbase = bx * BN + wn * 64;
    const int rquad = lane >> 2;          // 0..7
    const int cpair = (lane & 3) * 2;     // 0,2,4,6

    #pragma unroll
    for (int nt = 0; nt < 8; nt++) {
        const int col = nbase + nt * 8 + cpair;
        const float2 bf = *reinterpret_cast<const float2*>(bias + col);
        #pragma unroll
        for (int mt = 0; mt < 4; mt++) {
            const int row0 = mbase + mt * 16 + rquad;
            float r[4];
            #pragma unroll
            for (int q = 0; q < 4; q++) {
                float y = __half2float(__float2half_rn(acc[mt][nt][q]));
                r[q] = __half2float(__float2half_rn(y + ((q & 1) ? bf.y : bf.x)));
            }
            *reinterpret_cast<float2*>(out + (size_t)row0 * N_DIM + col) = make_float2(r[0], r[1]);
            *reinterpret_cast<float2*>(out + (size_t)(row0 + 8) * N_DIM + col) = make_float2(r[2], r[3]);
        }
    }
}

// ---------------- host launcher ----------------
// Inputs (fp16 arrays delivered upcast to fp32), identified by element count:
//   x=16777216 f32, qweight=22544384 i32, weight_scale=352256 f32 (first),
//   weight_zero=352256 i32 (second), bias=11008 f32
extern "C" void kernel_launch(void* const* d_in, const int* in_sizes, int n_in,
                              void* d_out, int out_size) {
    (void)out_size;
    const float* x    = nullptr;
    const int*   qw   = nullptr;
    const float* sc   = nullptr;
    const int*   zp   = nullptr;
    const float* bias = nullptr;

    for (int i = 0; i < n_in; i++) {
        const long long n = in_sizes[i];
        if (n == (long long)M_DIM * K_DIM)               x    = (const float*)d_in[i];
        else if (n == (long long)N_DIM * K_DIM / 2)      qw   = (const int*)d_in[i];
        else if (n == (long long)N_DIM * (K_DIM / 128)) {
            if (!sc) sc = (const float*)d_in[i];
            else     zp = (const int*)d_in[i];
        }
        else if (n == (long long)N_DIM)                  bias = (const float*)d_in[i];
    }
    float* out = (float*)d_out;

    prep_kernel<<<DEQ_BLOCKS + CVT_BLOCKS, 256>>>(qw, sc, zp, x);

    cudaFuncSetAttribute(gemm_kernel, cudaFuncAttributeMaxDynamicSharedMemorySize, SMEM_BYTES);
    gemm_kernel<<<NT_TILES * MT_TILES, THREADS, SMEM_BYTES>>>(bias, out);
}

// round 14
// speedup vs baseline: 1.2922x; 1.2922x over previous
#include <cuda_runtime.h>
#include <cuda_fp16.h>
#include <cstdint>

// ---------------- problem dims ----------------
#define M_DIM 4096
#define K_DIM 4096
#define N_DIM 11008

// GEMM tiling: CTA 128x128x64, 4 warps (2M x 2N), warp tile 64x64, 3 CTAs/SM
#define BM 128
#define BN 128
#define BK 64
#define STAGES 2
#define THREADS 128
#define KT (K_DIM / BK)          // 64
#define NT_TILES (N_DIM / BN)    // 86
#define MT_TILES (M_DIM / BM)    // 32
#define GROUP_M 16               // by varies fastest in groups of 16 (L2 wave shaping)

// padded smem rows: 64 halves (128B) + 16B pad = 144B stride
#define ROW_BYTES 144
#define A_STAGE_BYTES (BM * ROW_BYTES)                 // 18432
#define B_STAGE_BYTES (BN * ROW_BYTES)                 // 18432
#define STAGE_BYTES   (A_STAGE_BYTES + B_STAGE_BYTES)  // 36864
#define SMEM_BYTES    (STAGES * STAGE_BYTES)           // 73728 -> 3 CTAs/SM

// dequantized weights fp16 [N_DIM, K_DIM] K-major; x converted to fp16
__device__ __half g_w[(size_t)N_DIM * K_DIM];
__device__ __half g_x[(size_t)M_DIM * K_DIM];

// ---------------- helpers ----------------
__device__ __forceinline__ uint32_t smem_u32(const void* p) {
    return (uint32_t)__cvta_generic_to_shared(p);
}

__device__ __forceinline__ void cp_async16(uint32_t dst, const void* src) {
    asm volatile("cp.async.cg.shared.global [%0], [%1], 16;" :: "r"(dst), "l"(src));
}

__device__ __forceinline__ void ldsm4(uint32_t* r, uint32_t addr) {
    asm volatile("ldmatrix.sync.aligned.m8n8.x4.shared.b16 {%0,%1,%2,%3}, [%4];"
                 : "=r"(r[0]), "=r"(r[1]), "=r"(r[2]), "=r"(r[3]) : "r"(addr));
}

__device__ __forceinline__ void mma16816(float* d, const uint32_t* a, uint32_t b0, uint32_t b1) {
    asm volatile(
        "mma.sync.aligned.m16n8k16.row.col.f32.f16.f16.f32 "
        "{%0,%1,%2,%3}, {%4,%5,%6,%7}, {%8,%9}, {%0,%1,%2,%3};"
        : "+f"(d[0]), "+f"(d[1]), "+f"(d[2]), "+f"(d[3])
        : "r"(a[0]), "r"(a[1]), "r"(a[2]), "r"(a[3]), "r"(b0), "r"(b1));
}

__device__ __forceinline__ unsigned pack_h2(float lo, float hi) {
    __half2 h = __floats2half2_rn(lo, hi);
    return *reinterpret_cast<unsigned*>(&h);
}

// ---------------- kernel 1: fused prep (dequant W + convert x) ----------------
#define DEQ_BLOCKS ((N_DIM * 512) / 256)            // 22016
#define CVT_BLOCKS ((M_DIM * (K_DIM / 8)) / 256)    // 8192

__global__ void __launch_bounds__(256) prep_kernel(const int* __restrict__ qw,
                                                   const float* __restrict__ sc,
                                                   const int* __restrict__ zp,
                                                   const float* __restrict__ xf) {
    if (blockIdx.x < DEQ_BLOCKS) {
        int t = blockIdx.x * 256 + threadIdx.x;
        int o  = t >> 9;
        int p0 = (t & 511) << 2;
        const int4 q4 = *reinterpret_cast<const int4*>(qw + (size_t)o * 2048 + p0);
        int g = p0 >> 6;
        float scale = sc[o * 32 + g];
        float zero  = (float)zp[o * 32 + g];
        int qs[4] = {q4.x, q4.y, q4.z, q4.w};
        uint4 st;
        st.x = pack_h2(((float)(qs[0] & 0xF) - zero) * scale, ((float)((qs[0] >> 4) & 0xF) - zero) * scale);
        st.y = pack_h2(((float)(qs[1] & 0xF) - zero) * scale, ((float)((qs[1] >> 4) & 0xF) - zero) * scale);
        st.z = pack_h2(((float)(qs[2] & 0xF) - zero) * scale, ((float)((qs[2] >> 4) & 0xF) - zero) * scale);
        st.w = pack_h2(((float)(qs[3] & 0xF) - zero) * scale, ((float)((qs[3] >> 4) & 0xF) - zero) * scale);
        *reinterpret_cast<uint4*>(g_w + (size_t)o * K_DIM + 2 * p0) = st;
    } else {
        const size_t i = ((size_t)(blockIdx.x - DEQ_BLOCKS) * 256 + threadIdx.x) * 8;
        const float4 a = *reinterpret_cast<const float4*>(xf + i);
        const float4 b = *reinterpret_cast<const float4*>(xf + i + 4);
        uint4 st;
        st.x = pack_h2(a.x, a.y);
        st.y = pack_h2(a.z, a.w);
        st.z = pack_h2(b.x, b.y);
        st.w = pack_h2(b.z, b.w);
        *reinterpret_cast<uint4*>(g_x + i) = st;
    }
}

// ---------------- kernel 2: pipelined mma.sync GEMM ----------------
// out = f16(f16(x @ w^T) + bias) upcast to fp32. CTA 128x128x64,
// 4 warps (2M x 2N), warp tile 64x64, 2-stage smem pipeline, 3 CTAs/SM.
// Mainloop is the R11 form (ptxas schedules per-bt B loads best).
// 1D grid, by-fastest in GROUP_M=16: a wave's working set (~28 B tiles +
// ~16 A tiles ~ 44MB) stays L2-resident.

__device__ __forceinline__ uint32_t row_addr(uint32_t base, int row, int kc) {
    return base + row * ROW_BYTES + kc * 16;
}

__global__ void __launch_bounds__(THREADS, 3) gemm_kernel(
    const float* __restrict__ bias,
    float* __restrict__ out)
{
    extern __shared__ char smem[];
    const uint32_t sb = smem_u32(smem);

    const int tid  = threadIdx.x;
    const int wid  = tid >> 5;
    const int lane = tid & 31;
    const int wm = wid >> 1;        // 0..1  (M)
    const int wn = wid & 1;         // 0..1  (N)

    // wave-shaped tile mapping: by varies fastest within groups of GROUP_M
    const int id    = blockIdx.x;
    const int group = id / (GROUP_M * NT_TILES);
    const int rem   = id % (GROUP_M * NT_TILES);
    const int by    = group * GROUP_M + (rem % GROUP_M);   // 0..31
    const int bx    = rem / GROUP_M;                       // 0..85

    const __half* Ag = g_x + (size_t)(by * BM) * K_DIM;
    const __half* Bg = g_w + (size_t)(bx * BN) * K_DIM;

    const int ld_row = tid >> 3;        // 0..15 (+16 per i)
    const int ld_kc  = tid & 7;         // 16B chunk 0..7

    // prologue: fill stage 0
    {
        const uint32_t ab = sb;
        const uint32_t bb = ab + A_STAGE_BYTES;
        #pragma unroll
        for (int i = 0; i < 8; i++) {
            int row = ld_row + i * 16;
            cp_async16(row_addr(ab, row, ld_kc), Ag + (size_t)row * K_DIM + ld_kc * 8);
            cp_async16(row_addr(bb, row, ld_kc), Bg + (size_t)row * K_DIM + ld_kc * 8);
        }
        asm volatile("cp.async.commit_group;");
    }

    float acc[4][8][4];
    #pragma unroll
    for (int i = 0; i < 4; i++)
        #pragma unroll
        for (int j = 0; j < 8; j++)
            #pragma unroll
            for (int k = 0; k < 4; k++) acc[i][j][k] = 0.f;

    const int g  = lane >> 3;       // ldmatrix matrix-group 0..3
    const int r8 = lane & 7;

    for (int kt = 0; kt < KT; kt++) {
        asm volatile("cp.async.wait_group 0;");
        __syncthreads();

        const int s = kt & 1;
        const uint32_t abase = sb + s * STAGE_BYTES;
        const uint32_t bbase = abase + A_STAGE_BYTES;

        // prefetch stage kt+1 into the other buffer (readers done, per barrier above)
        if (kt + 1 < KT) {
            const uint32_t ab = sb + (s ^ 1) * STAGE_BYTES;
            const uint32_t bb = ab + A_STAGE_BYTES;
            const int kofs = (kt + 1) * BK;
            #pragma unroll
            for (int i = 0; i < 8; i++) {
                int row = ld_row + i * 16;
                cp_async16(row_addr(ab, row, ld_kc), Ag + (size_t)row * K_DIM + kofs + ld_kc * 8);
                cp_async16(row_addr(bb, row, ld_kc), Bg + (size_t)row * K_DIM + kofs + ld_kc * 8);
            }
        }
        asm volatile("cp.async.commit_group;");

        #pragma unroll
        for (int j = 0; j < 4; j++) {
            // A: 64 rows x k16 -> 4 ldsm4 (16 regs live)
            uint32_t a_frag[4][4];
            #pragma unroll
            for (int mt = 0; mt < 4; mt++) {
                int arow = wm * 64 + mt * 16 + ((g & 1) << 3) + r8;
                int kc = 2 * j + (g >> 1);
                ldsm4(a_frag[mt], row_addr(abase, arow, kc));
            }
            // B: 64 n-rows, loaded per-pair to bound live registers
            #pragma unroll
            for (int bt = 0; bt < 4; bt++) {
                uint32_t b_frag[4];
                int brow = wn * 64 + bt * 16 + ((g & 2) << 2) + r8;
                int kc = 2 * j + (g & 1);
                ldsm4(b_frag, row_addr(bbase, brow, kc));
                #pragma unroll
                for (int mt = 0; mt < 4; mt++) {
                    mma16816(acc[mt][bt * 2 + 0], a_frag[mt], b_frag[0], b_frag[1]);
                    mma16816(acc[mt][bt * 2 + 1], a_frag[mt], b_frag[2], b_frag[3]);
                }
            }
        }
    }

    // ---- epilogue: round like the reference (f16 matmul result, then f16 +bias) ----
    const int mbase = by * BM + wm * 64;
    const int nbase = bx * BN + wn * 64;
    const int rquad = lane >> 2;          // 0..7
    const int cpair = (lane & 3) * 2;     // 0,2,4,6

    #pragma unroll
    for (int nt = 0; nt < 8; nt++) {
        const int col = nbase + nt * 8 + cpair;
        const float2 bf = *reinterpret_cast<const float2*>(bias + col);
        #pragma unroll
        for (int mt = 0; mt < 4; mt++) {
            const int row0 = mbase + mt * 16 + rquad;
            float r[4];
            #pragma unroll
            for (int q = 0; q < 4; q++) {
                float y = __half2float(__float2half_rn(acc[mt][nt][q]));
                r[q] = __half2float(__float2half_rn(y + ((q & 1) ? bf.y : bf.x)));
            }
            *reinterpret_cast<float2*>(out + (size_t)row0 * N_DIM + col) = make_float2(r[0], r[1]);
            *reinterpret_cast<float2*>(out + (size_t)(row0 + 8) * N_DIM + col) = make_float2(r[2], r[3]);
        }
    }
}

// ---------------- host launcher ----------------
// Inputs (fp16 arrays delivered upcast to fp32), identified by element count:
//   x=16777216 f32, qweight=22544384 i32, weight_scale=352256 f32 (first),
//   weight_zero=352256 i32 (second), bias=11008 f32
extern "C" void kernel_launch(void* const* d_in, const int* in_sizes, int n_in,
                              void* d_out, int out_size) {
    (void)out_size;
    const float* x    = nullptr;
    const int*   qw   = nullptr;
    const float* sc   = nullptr;
    const int*   zp   = nullptr;
    const float* bias = nullptr;

    for (int i = 0; i < n_in; i++) {
        const long long n = in_sizes[i];
        if (n == (long long)M_DIM * K_DIM)               x    = (const float*)d_in[i];
        else if (n == (long long)N_DIM * K_DIM / 2)      qw   = (const int*)d_in[i];
        else if (n == (long long)N_DIM * (K_DIM / 128)) {
            if (!sc) sc = (const float*)d_in[i];
            else     zp = (const int*)d_in[i];
        }
        else if (n == (long long)N_DIM)                  bias = (const float*)d_in[i];
    }
    float* out = (float*)d_out;

    prep_kernel<<<DEQ_BLOCKS + CVT_BLOCKS, 256>>>(qw, sc, zp, x);

    cudaFuncSetAttribute(gemm_kernel, cudaFuncAttributeMaxDynamicSharedMemorySize, SMEM_BYTES);
    gemm_kernel<<<NT_TILES * MT_TILES, THREADS, SMEM_BYTES>>>(bias, out);
}

// round 15
// speedup vs baseline: 1.3688x; 1.0593x over previous
#include <cuda_runtime.h>
#include <cuda_fp16.h>
#include <cstdint>

// ---------------- problem dims ----------------
#define M_DIM 4096
#define K_DIM 4096
#define N_DIM 11008

// GEMM tiling: CTA 128x128x64, 4 warps (2M x 2N), warp tile 64x64, 3 CTAs/SM
#define BM 128
#define BN 128
#define BK 64
#define STAGES 2
#define THREADS 128
#define KT (K_DIM / BK)          // 64
#define NT_TILES (N_DIM / BN)    // 86
#define MT_TILES (M_DIM / BM)    // 32
#define GROUP_M 16               // by varies fastest in groups of 16 (L2 wave shaping)

// padded smem rows: 64 halves (128B) + 16B pad = 144B stride
#define ROW_BYTES 144
#define A_STAGE_BYTES (BM * ROW_BYTES)                 // 18432
#define B_STAGE_BYTES (BN * ROW_BYTES)                 // 18432
#define STAGE_BYTES   (A_STAGE_BYTES + B_STAGE_BYTES)  // 36864
#define SMEM_BYTES    (STAGES * STAGE_BYTES)           // 73728 -> 3 CTAs/SM

// dequantized weights fp16 [N_DIM, K_DIM] K-major; x converted to fp16
__device__ __half g_w[(size_t)N_DIM * K_DIM];
__device__ __half g_x[(size_t)M_DIM * K_DIM];

// ---------------- helpers ----------------
__device__ __forceinline__ uint32_t smem_u32(const void* p) {
    return (uint32_t)__cvta_generic_to_shared(p);
}

__device__ __forceinline__ void cp_async16(uint32_t dst, const void* src) {
    asm volatile("cp.async.cg.shared.global [%0], [%1], 16;" :: "r"(dst), "l"(src));
}

__device__ __forceinline__ void ldsm4(uint32_t* r, uint32_t addr) {
    asm volatile("ldmatrix.sync.aligned.m8n8.x4.shared.b16 {%0,%1,%2,%3}, [%4];"
                 : "=r"(r[0]), "=r"(r[1]), "=r"(r[2]), "=r"(r[3]) : "r"(addr));
}

__device__ __forceinline__ void mma16816(float* d, const uint32_t* a, uint32_t b0, uint32_t b1) {
    asm volatile(
        "mma.sync.aligned.m16n8k16.row.col.f32.f16.f16.f32 "
        "{%0,%1,%2,%3}, {%4,%5,%6,%7}, {%8,%9}, {%0,%1,%2,%3};"
        : "+f"(d[0]), "+f"(d[1]), "+f"(d[2]), "+f"(d[3])
        : "r"(a[0]), "r"(a[1]), "r"(a[2]), "r"(a[3]), "r"(b0), "r"(b1));
}

__device__ __forceinline__ unsigned pack_h2(float lo, float hi) {
    __half2 h = __floats2half2_rn(lo, hi);
    return *reinterpret_cast<unsigned*>(&h);
}

// ---------------- kernel 1: fused prep (dequant W + convert x) ----------------
#define DEQ_BLOCKS ((N_DIM * 512) / 256)            // 22016
#define CVT_BLOCKS ((M_DIM * (K_DIM / 8)) / 256)    // 8192

__global__ void __launch_bounds__(256) prep_kernel(const int* __restrict__ qw,
                                                   const float* __restrict__ sc,
                                                   const int* __restrict__ zp,
                                                   const float* __restrict__ xf) {
    if (blockIdx.x < DEQ_BLOCKS) {
        int t = blockIdx.x * 256 + threadIdx.x;
        int o  = t >> 9;
        int p0 = (t & 511) << 2;
        const int4 q4 = *reinterpret_cast<const int4*>(qw + (size_t)o * 2048 + p0);
        int g = p0 >> 6;
        float scale = sc[o * 32 + g];
        float zero  = (float)zp[o * 32 + g];
        int qs[4] = {q4.x, q4.y, q4.z, q4.w};
        uint4 st;
        st.x = pack_h2(((float)(qs[0] & 0xF) - zero) * scale, ((float)((qs[0] >> 4) & 0xF) - zero) * scale);
        st.y = pack_h2(((float)(qs[1] & 0xF) - zero) * scale, ((float)((qs[1] >> 4) & 0xF) - zero) * scale);
        st.z = pack_h2(((float)(qs[2] & 0xF) - zero) * scale, ((float)((qs[2] >> 4) & 0xF) - zero) * scale);
        st.w = pack_h2(((float)(qs[3] & 0xF) - zero) * scale, ((float)((qs[3] >> 4) & 0xF) - zero) * scale);
        *reinterpret_cast<uint4*>(g_w + (size_t)o * K_DIM + 2 * p0) = st;
    } else {
        const size_t i = ((size_t)(blockIdx.x - DEQ_BLOCKS) * 256 + threadIdx.x) * 8;
        const float4 a = *reinterpret_cast<const float4*>(xf + i);
        const float4 b = *reinterpret_cast<const float4*>(xf + i + 4);
        uint4 st;
        st.x = pack_h2(a.x, a.y);
        st.y = pack_h2(a.z, a.w);
        st.z = pack_h2(b.x, b.y);
        st.w = pack_h2(b.z, b.w);
        *reinterpret_cast<uint4*>(g_x + i) = st;
    }
}

// ---------------- kernel 2: pipelined mma.sync GEMM ----------------
// out = f16(f16(x @ w^T) + bias) upcast to fp32. CTA 128x128x64,
// 4 warps (2M x 2N), warp tile 64x64, 2-stage smem pipeline, 3 CTAs/SM.
// Per kt: barrier -> j=0 ldsm+MMA (tensor starts immediately) -> cp.async
// prefetch (hidden under draining HMMAs) -> j=1..3. No fragments live
// across the prefetch block (register pressure identical to the R11 form).

__device__ __forceinline__ uint32_t row_addr(uint32_t base, int row, int kc) {
    return base + row * ROW_BYTES + kc * 16;
}

__global__ void __launch_bounds__(THREADS, 3) gemm_kernel(
    const float* __restrict__ bias,
    float* __restrict__ out)
{
    extern __shared__ char smem[];
    const uint32_t sb = smem_u32(smem);

    const int tid  = threadIdx.x;
    const int wid  = tid >> 5;
    const int lane = tid & 31;
    const int wm = wid >> 1;        // 0..1  (M)
    const int wn = wid & 1;         // 0..1  (N)

    // wave-shaped tile mapping: by varies fastest within groups of GROUP_M
    const int id    = blockIdx.x;
    const int group = id / (GROUP_M * NT_TILES);
    const int rem   = id % (GROUP_M * NT_TILES);
    const int by    = group * GROUP_M + (rem % GROUP_M);   // 0..31
    const int bx    = rem / GROUP_M;                       // 0..85

    const __half* Ag = g_x + (size_t)(by * BM) * K_DIM;
    const __half* Bg = g_w + (size_t)(bx * BN) * K_DIM;

    const int ld_row = tid >> 3;        // 0..15 (+16 per i)
    const int ld_kc  = tid & 7;         // 16B chunk 0..7

    // prologue: fill stage 0
    {
        const uint32_t ab = sb;
        const uint32_t bb = ab + A_STAGE_BYTES;
        #pragma unroll
        for (int i = 0; i < 8; i++) {
            int row = ld_row + i * 16;
            cp_async16(row_addr(ab, row, ld_kc), Ag + (size_t)row * K_DIM + ld_kc * 8);
            cp_async16(row_addr(bb, row, ld_kc), Bg + (size_t)row * K_DIM + ld_kc * 8);
        }
        asm volatile("cp.async.commit_group;");
    }

    float acc[4][8][4];
    #pragma unroll
    for (int i = 0; i < 4; i++)
        #pragma unroll
        for (int j = 0; j < 8; j++)
            #pragma unroll
            for (int k = 0; k < 4; k++) acc[i][j][k] = 0.f;

    const int g  = lane >> 3;       // ldmatrix matrix-group 0..3
    const int r8 = lane & 7;

    const int a_row_off = wm * 64 + ((g & 1) << 3) + r8;   // + mt*16
    const int b_row_off = wn * 64 + ((g & 2) << 2) + r8;   // + bt*16
    const int a_kc_sel  = (g >> 1);                        // + 2j
    const int b_kc_sel  = (g & 1);                         // + 2j

    for (int kt = 0; kt < KT; kt++) {
        asm volatile("cp.async.wait_group 0;");
        __syncthreads();

        const int s = kt & 1;
        const uint32_t abase = sb + s * STAGE_BYTES;
        const uint32_t bbase = abase + A_STAGE_BYTES;

        // ---- j = 0: fragments + MMAs first, tensor pipe starts immediately ----
        {
            uint32_t a_frag[4][4];
            #pragma unroll
            for (int mt = 0; mt < 4; mt++)
                ldsm4(a_frag[mt], row_addr(abase, a_row_off + mt * 16, a_kc_sel));
            #pragma unroll
            for (int bt = 0; bt < 4; bt++) {
                uint32_t b_frag[4];
                ldsm4(b_frag, row_addr(bbase, b_row_off + bt * 16, b_kc_sel));
                #pragma unroll
                for (int mt = 0; mt < 4; mt++) {
                    mma16816(acc[mt][bt * 2 + 0], a_frag[mt], b_frag[0], b_frag[1]);
                    mma16816(acc[mt][bt * 2 + 1], a_frag[mt], b_frag[2], b_frag[3]);
                }
            }
        }

        // ---- prefetch stage kt+1 (hidden under j=0's draining HMMAs) ----
        if (kt + 1 < KT) {
            const uint32_t ab = sb + (s ^ 1) * STAGE_BYTES;
            const uint32_t bb = ab + A_STAGE_BYTES;
            const int kofs = (kt + 1) * BK;
            #pragma unroll
            for (int i = 0; i < 8; i++) {
                int row = ld_row + i * 16;
                cp_async16(row_addr(ab, row, ld_kc), Ag + (size_t)row * K_DIM + kofs + ld_kc * 8);
                cp_async16(row_addr(bb, row, ld_kc), Bg + (size_t)row * K_DIM + kofs + ld_kc * 8);
            }
        }
        asm volatile("cp.async.commit_group;");

        // ---- j = 1..3 ----
        #pragma unroll
        for (int j = 1; j < 4; j++) {
            const int akc = 2 * j + a_kc_sel;
            const int bkc = 2 * j + b_kc_sel;
            uint32_t a_frag[4][4];
            #pragma unroll
            for (int mt = 0; mt < 4; mt++)
                ldsm4(a_frag[mt], row_addr(abase, a_row_off + mt * 16, akc));
            #pragma unroll
            for (int bt = 0; bt < 4; bt++) {
                uint32_t b_frag[4];
                ldsm4(b_frag, row_addr(bbase, b_row_off + bt * 16, bkc));
                #pragma unroll
                for (int mt = 0; mt < 4; mt++) {
                    mma16816(acc[mt][bt * 2 + 0], a_frag[mt], b_frag[0], b_frag[1]);
                    mma16816(acc[mt][bt * 2 + 1], a_frag[mt], b_frag[2], b_frag[3]);
                }
            }
        }
    }

    // ---- epilogue: round like the reference (f16 matmul result, then f16 +bias) ----
    const int mbase = by * BM + wm * 64;
    const int nbase = bx * BN + wn * 64;
    const int rquad = lane >> 2;          // 0..7
    const int cpair = (lane & 3) * 2;     // 0,2,4,6

    #pragma unroll
    for (int nt = 0; nt < 8; nt++) {
        const int col = nbase + nt * 8 + cpair;
        const float2 bf = *reinterpret_cast<const float2*>(bias + col);
        #pragma unroll
        for (int mt = 0; mt < 4; mt++) {
            const int row0 = mbase + mt * 16 + rquad;
            float r[4];
            #pragma unroll
            for (int q = 0; q < 4; q++) {
                float y = __half2float(__float2half_rn(acc[mt][nt][q]));
                r[q] = __half2float(__float2half_rn(y + ((q & 1) ? bf.y : bf.x)));
            }
            *reinterpret_cast<float2*>(out + (size_t)row0 * N_DIM + col) = make_float2(r[0], r[1]);
            *reinterpret_cast<float2*>(out + (size_t)(row0 + 8) * N_DIM + col) = make_float2(r[2], r[3]);
        }
    }
}

// ---------------- host launcher ----------------
// Inputs (fp16 arrays delivered upcast to fp32), identified by element count:
//   x=16777216 f32, qweight=22544384 i32, weight_scale=352256 f32 (first),
//   weight_zero=352256 i32 (second), bias=11008 f32
extern "C" void kernel_launch(void* const* d_in, const int* in_sizes, int n_in,
                              void* d_out, int out_size) {
    (void)out_size;
    const float* x    = nullptr;
    const int*   qw   = nullptr;
    const float* sc   = nullptr;
    const int*   zp   = nullptr;
    const float* bias = nullptr;

    for (int i = 0; i < n_in; i++) {
        const long long n = in_sizes[i];
        if (n == (long long)M_DIM * K_DIM)               x    = (const float*)d_in[i];
        else if (n == (long long)N_DIM * K_DIM / 2)      qw   = (const int*)d_in[i];
        else if (n == (long long)N_DIM * (K_DIM / 128)) {
            if (!sc) sc = (const float*)d_in[i];
            else     zp = (const int*)d_in[i];
        }
        else if (n == (long long)N_DIM)                  bias = (const float*)d_in[i];
    }
    float* out = (float*)d_out;

    prep_kernel<<<DEQ_BLOCKS + CVT_BLOCKS, 256>>>(qw, sc, zp, x);

    cudaFuncSetAttribute(gemm_kernel, cudaFuncAttributeMaxDynamicSharedMemorySize, SMEM_BYTES);
    gemm_kernel<<<NT_TILES * MT_TILES, THREADS, SMEM_BYTES>>>(bias, out);
}